// round 10
// baseline (speedup 1.0000x reference)
#include <cuda_runtime.h>
#include <math.h>

#define BATCH  2
#define KPATCH 1600
#define DDIM   1024
#define CCLS   256
#define NBOX   32
#define PGRID  40
#define BN     (BATCH*NBOX)            /* 64 */
#define QSPLIT 3
#define NQBLK  (QSPLIT*BN)             /* 192 q blocks */
#define NBLOCKS 256                    /* 192 q + 64 misc; all co-resident (148*2) */

// ---------------- scratch (static device globals; no allocation) ----------------
__device__ float g_eninv[CCLS];
__device__ float g_cntinv[BN];
__device__ float g_Qpart[QSPLIT*BN*DDIM];

// grid barrier (sense-reversal; self-resetting across graph replays)
__device__ unsigned g_bar_count = 0;
__device__ volatile unsigned g_bar_gen = 0;

__device__ __forceinline__ void grid_barrier() {
    __syncthreads();
    if (threadIdx.x == 0) {
        __threadfence();
        unsigned gen = g_bar_gen;
        unsigned old = atomicAdd(&g_bar_count, 1);
        if (old == NBLOCKS - 1) {
            g_bar_count = 0;
            __threadfence();
            g_bar_gen = gen + 1;
        } else {
            while (g_bar_gen == gen) { __nanosleep(32); }
        }
        __threadfence();
    }
    __syncthreads();
}

// Keys cubic, a = -0.5 (matches jax.image.resize 'bicubic')
__device__ __forceinline__ float cubicf(float x) {   // x >= 0
    if (x < 1.f) return ((1.5f*x - 2.5f)*x)*x + 1.f;
    if (x < 2.f) return ((-0.5f*x + 2.5f)*x - 4.f)*x + 2.f;
    return 0.f;
}

// ---------------- single fused kernel -------------------------------------------
__global__ void __launch_bounds__(256, 2) fused_kernel(
        const float* __restrict__ feats,
        const float* __restrict__ emb,
        const int* __restrict__ boxes,
        float* __restrict__ out) {
    __shared__ union {
        struct {                                  // phase A (q blocks)
            float sv[2*PGRID];                    // vy[0..39], vx[40..79]
            unsigned short taps[256];             // p*40+q per tap
            float wt[256];                        // vy[p]*vx[q] per tap
            float red[8*DDIM];                    // per-warp partials (32KB)
        } a;
        struct {                                  // phase B (GEMM tiles)
            float Qs[16*64];                      // [bn][dd]  4KB
            float Es[32*68];                      // [c][dd]   8.5KB
        } b;
    } sm;

    int blk  = blockIdx.x;
    int t    = threadIdx.x;
    int warp = t >> 5, lane = t & 31;

    // =================== Phase A ==============================================
    if (blk >= NQBLK) {
        // ---- misc: 4 emb-row norms (2 warps/row, MLP=4) + zero out slice ------
        int m = blk - NQBLK;
        __shared__ float ws[8];
        int row  = m * 4 + (warp >> 1);
        int half = warp & 1;
        const float4* p4 = (const float4*)(emb) + (size_t)row * 256 + half * 128;
        float4 v[4];
        #pragma unroll
        for (int i = 0; i < 4; ++i) v[i] = p4[lane + 32*i];
        float ss = 0.f;
        #pragma unroll
        for (int i = 0; i < 4; ++i)
            ss += v[i].x*v[i].x + v[i].y*v[i].y + v[i].z*v[i].z + v[i].w*v[i].w;
        #pragma unroll
        for (int o = 16; o; o >>= 1) ss += __shfl_xor_sync(0xffffffffu, ss, o);
        if (lane == 0) ws[warp] = ss;
        out[m * CCLS + t] = 0.f;                  // zero output (64x256 total)
        __syncthreads();
        if (t < 4) g_eninv[m*4 + t] = 1.0f / sqrtf(ws[2*t] + ws[2*t+1]);
    } else {
        int s  = blk % QSPLIT;
        int bn = blk / QSPLIT;
        int b  = bn >> 5;

        int x_min = boxes[bn*4+0], y_min = boxes[bn*4+1];
        int x_max = boxes[bn*4+2], y_max = boxes[bn*4+3];
        if (t < 2*PGRID) sm.a.sv[t] = 0.f;
        __syncthreads();

        // ---- pixel-parallel bicubic tap weight accumulation -------------------
        int ny = y_max - 1 - y_min;
        int nx = x_max - 1 - x_min;
        for (int i = t; i < ny + nx; i += 256) {
            int y; float* dst;
            if (i < ny) { y = y_min + i;        dst = sm.a.sv; }
            else        { y = x_min + (i - ny); dst = sm.a.sv + PGRID; }
            float sf = (y + 0.5f) * (1.0f/14.0f) - 0.5f;
            int i0 = (int)floorf(sf);
            float w[4]; float cs = 0.f;
            #pragma unroll
            for (int j = 0; j < 4; ++j) {
                int ii = i0 - 1 + j;
                float c = (ii >= 0 && ii < PGRID) ? cubicf(fabsf(sf - (float)ii)) : 0.f;
                w[j] = c; cs += c;
            }
            float inv = __fdividef(1.0f, cs);
            #pragma unroll
            for (int j = 0; j < 4; ++j) {
                int ii = i0 - 1 + j;
                if (ii >= 0 && ii < PGRID && w[j] != 0.f)
                    atomicAdd(&dst[ii], w[j] * inv);
            }
        }
        if (t == 0 && s == 0)
            g_cntinv[bn] = __fdividef(1.0f, (float)(ny * nx));
        __syncthreads();

        // ---- tap rectangle + tap list (one int-div per thread, setup only) ----
        float sfl = (y_min + 0.5f) * (1.0f/14.0f) - 0.5f;
        float sfh = (y_max - 2 + 0.5f) * (1.0f/14.0f) - 0.5f;
        int p0 = max(0, (int)floorf(sfl) - 1);
        int p1 = min(PGRID - 1, (int)floorf(sfh) + 2);
        sfl = (x_min + 0.5f) * (1.0f/14.0f) - 0.5f;
        sfh = (x_max - 2 + 0.5f) * (1.0f/14.0f) - 0.5f;
        int q0 = max(0, (int)floorf(sfl) - 1);
        int q1 = min(PGRID - 1, (int)floorf(sfh) + 2);
        int nq = q1 - q0 + 1;
        int ntaps = (p1 - p0 + 1) * nq;           // <= 225

        if (t < ntaps) {
            int pi = t / nq;
            int qi = t - pi * nq;
            int p = p0 + pi, q = q0 + qi;
            sm.a.taps[t] = (unsigned short)(p * PGRID + q);
            sm.a.wt[t]   = sm.a.sv[p] * sm.a.sv[PGRID + q];
        }
        __syncthreads();

        // ---- warp-slot tap-pair accumulation with inline norms ----------------
        // 24 warp-slots (3 blocks x 8 warps) take taps interleaved mod 24.
        int slot = s * 8 + warp;
        float4 acc[8];
        #pragma unroll
        for (int i = 0; i < 8; ++i) acc[i] = make_float4(0.f,0.f,0.f,0.f);

        const float4* f4 = (const float4*)feats + (size_t)b * KPATCH * 256;
        for (int i0t = slot; i0t < ntaps; i0t += 48) {
            int i1t  = i0t + 24;
            bool has1 = (i1t < ntaps);
            int k0 = sm.a.taps[i0t];
            int k1 = sm.a.taps[has1 ? i1t : i0t];
            const float4* r0 = f4 + (size_t)k0 * 256;
            const float4* r1 = f4 + (size_t)k1 * 256;
            float4 v0[8], v1[8];
            #pragma unroll
            for (int i = 0; i < 8; ++i) v0[i] = r0[lane + 32*i];
            #pragma unroll
            for (int i = 0; i < 8; ++i) v1[i] = r1[lane + 32*i];
            float s0 = 0.f, s1 = 0.f;
            #pragma unroll
            for (int i = 0; i < 8; ++i) {
                s0 += v0[i].x*v0[i].x + v0[i].y*v0[i].y + v0[i].z*v0[i].z + v0[i].w*v0[i].w;
                s1 += v1[i].x*v1[i].x + v1[i].y*v1[i].y + v1[i].z*v1[i].z + v1[i].w*v1[i].w;
            }
            #pragma unroll
            for (int o = 16; o; o >>= 1) {
                s0 += __shfl_xor_sync(0xffffffffu, s0, o);
                s1 += __shfl_xor_sync(0xffffffffu, s1, o);
            }
            float w0 = sm.a.wt[i0t] * (1.0f / sqrtf(s0));
            float w1 = has1 ? sm.a.wt[i1t] * (1.0f / sqrtf(s1)) : 0.f;
            #pragma unroll
            for (int i = 0; i < 8; ++i) {
                acc[i].x += w0 * v0[i].x + w1 * v1[i].x;
                acc[i].y += w0 * v0[i].y + w1 * v1[i].y;
                acc[i].z += w0 * v0[i].z + w1 * v1[i].z;
                acc[i].w += w0 * v0[i].w + w1 * v1[i].w;
            }
        }

        // ---- block reduce over 8 warps ----------------------------------------
        #pragma unroll
        for (int i = 0; i < 8; ++i)
            ((float4*)sm.a.red)[warp*256 + lane + 32*i] = acc[i];
        __syncthreads();
        float4 sum = make_float4(0.f,0.f,0.f,0.f);
        #pragma unroll
        for (int w = 0; w < 8; ++w) {
            float4 a = ((const float4*)sm.a.red)[w*256 + t];
            sum.x += a.x; sum.y += a.y; sum.z += a.z; sum.w += a.w;
        }
        ((float4*)g_Qpart)[(size_t)(s*BN + bn) * 256 + t] = sum;
    }

    grid_barrier();   // Qpart, eninv, cntinv, zeroed out all visible

    // =================== Phase B: 512 GEMM tiles, 2 per block ==================
    #pragma unroll
    for (int rep = 0; rep < 2; ++rep) {
        int T   = blk + rep * NBLOCKS;
        int c0  = (T & 7) * 32;
        int d0  = ((T >> 3) & 15) * 64;
        int bn0 = (T >> 7) * 16;

        {   // Q tile: 256 float4 (16 bn x 16 dd4), sum QSPLIT partials
            int bn = t >> 4, dd4 = t & 15;
            const float4* qp4 = (const float4*)g_Qpart;
            float4 v = make_float4(0.f,0.f,0.f,0.f);
            #pragma unroll
            for (int sp = 0; sp < QSPLIT; ++sp) {
                float4 a = qp4[(size_t)(sp*BN + bn0 + bn) * 256 + (d0>>2) + dd4];
                v.x += a.x; v.y += a.y; v.z += a.z; v.w += a.w;
            }
            ((float4*)sm.b.Qs)[bn*16 + dd4] = v;
        }
        const float4* e4 = (const float4*)emb;
        #pragma unroll
        for (int i = 0; i < 2; ++i) {
            int lin = i * 256 + t;
            int c = lin >> 4, dd4 = lin & 15;
            float sc = g_eninv[c0 + c];
            float4 a = e4[(size_t)(c0 + c) * 256 + (d0>>2) + dd4];
            a.x *= sc; a.y *= sc; a.z *= sc; a.w *= sc;
            *(float4*)&sm.b.Es[c*68 + dd4*4] = a;
        }
        __syncthreads();

        int c = t & 31, g = t >> 5;
        float acc2[2] = {0.f, 0.f};
        #pragma unroll
        for (int dd4 = 0; dd4 < 16; ++dd4) {
            float4 e = *(const float4*)&sm.b.Es[c*68 + dd4*4];
            #pragma unroll
            for (int j = 0; j < 2; ++j) {
                float4 q = ((const float4*)sm.b.Qs)[(g*2 + j)*16 + dd4];
                acc2[j] += q.x*e.x + q.y*e.y + q.z*e.z + q.w*e.w;
            }
        }
        #pragma unroll
        for (int j = 0; j < 2; ++j) {
            int bn = bn0 + g*2 + j;
            atomicAdd(&out[bn*CCLS + c0 + c], acc2[j] * g_cntinv[bn]);
        }
        __syncthreads();   // smem reuse safety for rep=1
    }
}

// ---------------- launch --------------------------------------------------------
extern "C" void kernel_launch(void* const* d_in, const int* in_sizes, int n_in,
                              void* d_out, int out_size) {
    (void)in_sizes; (void)n_in; (void)out_size;
    const float* feats = (const float*)d_in[0];
    const float* emb   = (const float*)d_in[1];
    const int*   boxes = (const int*)d_in[2];
    float* out = (float*)d_out;

    fused_kernel<<<NBLOCKS, 256>>>(feats, emb, boxes, out);
}

// round 11
// speedup vs baseline: 1.1235x; 1.1235x over previous
#include <cuda_runtime.h>
#include <math.h>

#define BATCH  2
#define KPATCH 1600
#define DDIM   1024
#define CCLS   256
#define NBOX   32
#define PGRID  40
#define BN     (BATCH*NBOX)            /* 64 */
#define QSPLIT 6
#define NSLOTS (QSPLIT*8)              /* 48 warp-slots per box */

// ---------------- scratch (static device globals; no allocation) ----------------
__device__ float g_eninv[CCLS];
__device__ float g_cntinv[BN];
__device__ float g_Qpart[QSPLIT*BN*DDIM];

// Keys cubic, a = -0.5 (matches jax.image.resize 'bicubic')
__device__ __forceinline__ float cubicf(float x) {   // x >= 0
    if (x < 1.f) return ((1.5f*x - 2.5f)*x)*x + 1.f;
    if (x < 2.f) return ((-0.5f*x + 2.5f)*x - 4.f)*x + 2.f;
    return 0.f;
}

// ---------------- kernel 1: Q partials, high-occupancy single-tap loop ----------
// grid (QSPLIT+1, BN). s<QSPLIT: Q work. s==QSPLIT: misc (emb norms + zero out).
__global__ void __launch_bounds__(256, 3) q_kernel(
        const float* __restrict__ feats,
        const float* __restrict__ emb,
        const int* __restrict__ boxes,
        float* __restrict__ out) {
    int s    = blockIdx.x;
    int bn   = blockIdx.y;
    int t    = threadIdx.x;
    int warp = t >> 5, lane = t & 31;

    if (s == QSPLIT) {
        // ---- misc: 4 emb-row norms (2 warps/row, MLP=4) + zero out slice ------
        __shared__ float ws[8];
        int row  = bn * 4 + (warp >> 1);
        int half = warp & 1;
        const float4* p4 = (const float4*)(emb) + (size_t)row * 256 + half * 128;
        float4 v[4];
        #pragma unroll
        for (int i = 0; i < 4; ++i) v[i] = p4[lane + 32*i];
        float ss = 0.f;
        #pragma unroll
        for (int i = 0; i < 4; ++i)
            ss += v[i].x*v[i].x + v[i].y*v[i].y + v[i].z*v[i].z + v[i].w*v[i].w;
        #pragma unroll
        for (int o = 16; o; o >>= 1) ss += __shfl_xor_sync(0xffffffffu, ss, o);
        if (lane == 0) ws[warp] = ss;
        out[bn * CCLS + t] = 0.f;              // zero output (64 blocks x 256)
        __syncthreads();
        if (t < 4) g_eninv[bn*4 + t] = 1.0f / sqrtf(ws[2*t] + ws[2*t+1]);
        return;
    }

    __shared__ float sv[2*PGRID];              // vy[0..39], vx[40..79]
    __shared__ unsigned short taps[256];       // p*40+q per tap
    __shared__ float wt[256];                  // vy[p]*vx[q]
    __shared__ float red[8*DDIM];              // per-warp partials (32KB)

    int x_min = boxes[bn*4+0], y_min = boxes[bn*4+1];
    int x_max = boxes[bn*4+2], y_max = boxes[bn*4+3];
    if (t < 2*PGRID) sv[t] = 0.f;
    __syncthreads();

    // ---- pixel-parallel bicubic tap weight accumulation -----------------------
    int ny = y_max - 1 - y_min;
    int nx = x_max - 1 - x_min;
    for (int i = t; i < ny + nx; i += 256) {
        int y; float* dst;
        if (i < ny) { y = y_min + i;        dst = sv; }
        else        { y = x_min + (i - ny); dst = sv + PGRID; }
        float sf = (y + 0.5f) * (1.0f/14.0f) - 0.5f;
        int i0 = (int)floorf(sf);
        float w[4]; float cs = 0.f;
        #pragma unroll
        for (int j = 0; j < 4; ++j) {
            int ii = i0 - 1 + j;
            float c = (ii >= 0 && ii < PGRID) ? cubicf(fabsf(sf - (float)ii)) : 0.f;
            w[j] = c; cs += c;
        }
        float inv = __fdividef(1.0f, cs);
        #pragma unroll
        for (int j = 0; j < 4; ++j) {
            int ii = i0 - 1 + j;
            if (ii >= 0 && ii < PGRID && w[j] != 0.f)
                atomicAdd(&dst[ii], w[j] * inv);
        }
    }
    if (t == 0 && s == 0)
        g_cntinv[bn] = __fdividef(1.0f, (float)(ny * nx));
    __syncthreads();

    // ---- tap rectangle + tap list (one int-div per thread, setup only) --------
    float sfl = (y_min + 0.5f) * (1.0f/14.0f) - 0.5f;
    float sfh = (y_max - 2 + 0.5f) * (1.0f/14.0f) - 0.5f;
    int p0 = max(0, (int)floorf(sfl) - 1);
    int p1 = min(PGRID - 1, (int)floorf(sfh) + 2);
    sfl = (x_min + 0.5f) * (1.0f/14.0f) - 0.5f;
    sfh = (x_max - 2 + 0.5f) * (1.0f/14.0f) - 0.5f;
    int q0 = max(0, (int)floorf(sfl) - 1);
    int q1 = min(PGRID - 1, (int)floorf(sfh) + 2);
    int nq = q1 - q0 + 1;
    int ntaps = (p1 - p0 + 1) * nq;            // <= 225

    if (t < ntaps) {
        int pi = t / nq;
        int qi = t - pi * nq;
        int p = p0 + pi, q = q0 + qi;
        taps[t] = (unsigned short)(p * PGRID + q);
        wt[t]   = sv[p] * sv[PGRID + q];
    }
    __syncthreads();

    // ---- warp-slot single-tap accumulation with inline norm -------------------
    int slot = s * 8 + warp;                   // 0..47
    int b    = bn >> 5;
    float4 acc[8];
    #pragma unroll
    for (int i = 0; i < 8; ++i) acc[i] = make_float4(0.f,0.f,0.f,0.f);

    const float4* f4 = (const float4*)feats + (size_t)b * KPATCH * 256;
    for (int it = slot; it < ntaps; it += NSLOTS) {
        const float4* r = f4 + (size_t)taps[it] * 256;
        float4 v[8];
        #pragma unroll
        for (int i = 0; i < 8; ++i) v[i] = r[lane + 32*i];     // MLP=8
        float ss = 0.f;
        #pragma unroll
        for (int i = 0; i < 8; ++i)
            ss += v[i].x*v[i].x + v[i].y*v[i].y + v[i].z*v[i].z + v[i].w*v[i].w;
        #pragma unroll
        for (int o = 16; o; o >>= 1) ss += __shfl_xor_sync(0xffffffffu, ss, o);
        float w = wt[it] * (1.0f / sqrtf(ss));
        #pragma unroll
        for (int i = 0; i < 8; ++i) {
            acc[i].x += w * v[i].x; acc[i].y += w * v[i].y;
            acc[i].z += w * v[i].z; acc[i].w += w * v[i].w;
        }
    }

    // ---- block reduce over 8 warps --------------------------------------------
    #pragma unroll
    for (int i = 0; i < 8; ++i)
        ((float4*)red)[warp*256 + lane + 32*i] = acc[i];
    __syncthreads();
    float4 sum = make_float4(0.f,0.f,0.f,0.f);
    #pragma unroll
    for (int w = 0; w < 8; ++w) {
        float4 a = ((const float4*)red)[w*256 + t];
        sum.x += a.x; sum.y += a.y; sum.z += a.z; sum.w += a.w;
    }
    ((float4*)g_Qpart)[(size_t)(s*BN + bn) * 256 + t] = sum;
}

// ---------------- kernel 2: out += (Q @ embT) * cntinv  (bn-split, 512 blocks) --
__global__ void __launch_bounds__(256) out_kernel(const float* __restrict__ emb,
                                                  float* __restrict__ out) {
    __shared__ float Qs[16 * 64];      // [bn][dd]  4KB (16-bn slice)
    __shared__ float Es[32 * 68];      // [c][dd]   8.5KB, stride 68
    int c0  = blockIdx.x * 32;
    int d0  = blockIdx.y * 64;
    int bn0 = blockIdx.z * 16;
    int t   = threadIdx.x;

    {   // Q tile: 256 float4 (16 bn x 16 dd4), sum QSPLIT partials
        int bn = t >> 4, dd4 = t & 15;
        const float4* qp4 = (const float4*)g_Qpart;
        float4 v = make_float4(0.f,0.f,0.f,0.f);
        #pragma unroll
        for (int sp = 0; sp < QSPLIT; ++sp) {
            float4 a = qp4[(size_t)(sp*BN + bn0 + bn) * 256 + (d0>>2) + dd4];
            v.x += a.x; v.y += a.y; v.z += a.z; v.w += a.w;
        }
        ((float4*)Qs)[bn*16 + dd4] = v;
    }
    const float4* e4 = (const float4*)emb;
    #pragma unroll
    for (int i = 0; i < 2; ++i) {
        int lin = i * 256 + t;             // 0..511
        int c = lin >> 4, dd4 = lin & 15;
        float sc = g_eninv[c0 + c];
        float4 a = e4[(size_t)(c0 + c) * 256 + (d0>>2) + dd4];
        a.x *= sc; a.y *= sc; a.z *= sc; a.w *= sc;
        *(float4*)&Es[c*68 + dd4*4] = a;
    }
    __syncthreads();

    int c = t & 31, g = t >> 5;            // 8 groups x 2 bn each
    float acc[2] = {0.f, 0.f};
    #pragma unroll
    for (int dd4 = 0; dd4 < 16; ++dd4) {
        float4 e = *(const float4*)&Es[c*68 + dd4*4];
        #pragma unroll
        for (int j = 0; j < 2; ++j) {
            float4 q = ((const float4*)Qs)[(g*2 + j)*16 + dd4];   // broadcast
            acc[j] += q.x*e.x + q.y*e.y + q.z*e.z + q.w*e.w;
        }
    }
    #pragma unroll
    for (int j = 0; j < 2; ++j) {
        int bn = bn0 + g*2 + j;
        atomicAdd(&out[bn*CCLS + c0 + c], acc[j] * g_cntinv[bn]);
    }
}

// ---------------- launch --------------------------------------------------------
extern "C" void kernel_launch(void* const* d_in, const int* in_sizes, int n_in,
                              void* d_out, int out_size) {
    (void)in_sizes; (void)n_in; (void)out_size;
    const float* feats = (const float*)d_in[0];
    const float* emb   = (const float*)d_in[1];
    const int*   boxes = (const int*)d_in[2];
    float* out = (float*)d_out;

    q_kernel<<<dim3(QSPLIT + 1, BN), 256>>>(feats, emb, boxes, out);
    out_kernel<<<dim3(CCLS/32, DDIM/64, BN/16), 256>>>(emb, out);
}